// round 3
// baseline (speedup 1.0000x reference)
#include <cuda_runtime.h>
#include <math.h>

#define BB 128
#define NP 256
#define NN (BB*NP)        // 32768 nodes
#define EP 2048
#define EE (2*BB*EP)      // 524288 edges (symmetrized)
#define HH 128
#define DIMS 128
#define NHEADS 8
#define DKK 16
#define C1N 32
#define C2N 64
#define NCN 10

typedef unsigned long long u64;

// ---------------- packed f32x2 helpers (FFMA2 path; ptxas never emits these from C++) ----
__device__ __forceinline__ u64 pk2(float lo, float hi){
  u64 r; asm("mov.b64 %0,{%1,%2};":"=l"(r):"f"(lo),"f"(hi)); return r;
}
__device__ __forceinline__ u64 pkdup(float v){ return pk2(v, v); }
__device__ __forceinline__ float2 up2(u64 v){
  float2 r; asm("mov.b64 {%0,%1},%2;":"=f"(r.x),"=f"(r.y):"l"(v)); return r;
}
__device__ __forceinline__ void fma2(u64 &d, u64 a, u64 b){
  asm("fma.rn.f32x2 %0,%1,%2,%0;":"+l"(d):"l"(a),"l"(b));
}
__device__ __forceinline__ u64 mul2(u64 a, u64 b){
  u64 d; asm("mul.rn.f32x2 %0,%1,%2;":"=l"(d):"l"(a),"l"(b)); return d;
}

// ---------------- scratch (device globals; no allocations allowed) ----------------
__device__ float  g_dnorm[NN];
__device__ int    g_cnt[NN];
__device__ int    g_cnt2[NN];
__device__ int    g_rowptr[NN+1];
__device__ int    g_col[EE];
__device__ float  g_h[NN*HH];          // current node features
__device__ float  g_t[NN*HH];          // (dnorm*h)@W before aggregation
__device__ double g_sv[NN];            // score pre-aggregation (dnorm*h@Wp), fp64
__device__ float  g_xp[BB*DIMS*HH];
__device__ float  g_q[BB*DIMS*HH];
__device__ float  g_k[BB*DIMS*HH];
__device__ float  g_v[BB*DIMS*HH];
__device__ float  g_xs[BB*3*DIMS*HH];  // stacked MHSA outputs [B][3][DIMS][H]

// ---------------- CSR build ----------------
__global__ void k_zero_cnt(){
  int i = blockIdx.x*blockDim.x + threadIdx.x;
  if (i < NN){ g_cnt[i] = 0; g_cnt2[i] = 0; }
}

__global__ void k_count(const int* __restrict__ dst){
  int i = blockIdx.x*blockDim.x + threadIdx.x;
  if (i < EE) atomicAdd(&g_cnt[dst[i]], 1);
}

// one-block exclusive scan of 32768 counts (1024 threads x 32 each)
__global__ void k_scan(){
  __shared__ int ss[1024];
  int tid = threadIdx.x;
  int base = tid*32;
  int loc[32]; int s = 0;
  #pragma unroll
  for (int i = 0; i < 32; i++){ loc[i] = g_cnt[base+i]; s += loc[i]; }
  ss[tid] = s; __syncthreads();
  for (int off = 1; off < 1024; off <<= 1){
    int v = 0;
    if (tid >= off) v = ss[tid-off];
    __syncthreads();
    if (tid >= off) ss[tid] += v;
    __syncthreads();
  }
  int run = ss[tid] - s;   // exclusive prefix
  #pragma unroll
  for (int i = 0; i < 32; i++){ g_rowptr[base+i] = run; run += loc[i]; }
  if (tid == 1023) g_rowptr[NN] = run;
}

__global__ void k_fill(const int* __restrict__ src, const int* __restrict__ dst){
  int i = blockIdx.x*blockDim.x + threadIdx.x;
  if (i < EE){
    int d = dst[i];
    int pos = g_rowptr[d] + atomicAdd(&g_cnt2[d], 1);
    g_col[pos] = src[i];
  }
}

// sort each row ascending -> canonical deterministic reduction order; also dnorm
__global__ void k_sort_dnorm(){
  int n = blockIdx.x*blockDim.x + threadIdx.x;
  if (n >= NN) return;
  int s0 = g_rowptr[n], s1 = g_rowptr[n+1];
  int len = s1 - s0;
  if (len <= 64){
    int buf[64];
    for (int i = 0; i < len; i++) buf[i] = g_col[s0+i];
    for (int i = 1; i < len; i++){
      int key = buf[i]; int j = i-1;
      while (j >= 0 && buf[j] > key){ buf[j+1] = buf[j]; j--; }
      buf[j+1] = key;
    }
    for (int i = 0; i < len; i++) g_col[s0+i] = buf[i];
  } else {
    for (int i = s0+1; i < s1; i++){
      int key = g_col[i]; int j = i-1;
      while (j >= s0 && g_col[j] > key){ g_col[j+1] = g_col[j]; j--; }
      g_col[j+1] = key;
    }
  }
  g_dnorm[n] = rsqrtf(fmaxf((float)len, 1.0f));
}

// ---------------- GEMM: O[M,128] = (A .* scale?) @ W[128,128], fp32, FFMA2 ----------------
// A tile (128x128) fully resident in smem; up to 3 weight matrices reuse it (QKV fusion).
// grid.x = M/128, 256 threads, each thread computes 8x8 (as 8x4 packed pairs).
__global__ void __launch_bounds__(256) k_gemm3(const float* __restrict__ A,
                                               const float* __restrict__ scale,
                                               const float* __restrict__ W0, float* __restrict__ O0,
                                               const float* __restrict__ W1, float* __restrict__ O1,
                                               const float* __restrict__ W2, float* __restrict__ O2){
  __shared__ float As[128][128];   // [k][m], 64KB
  __shared__ float Bs[8][128];
  int tid = threadIdx.x;
  int tx = tid & 15, ty = tid >> 4;
  int br = blockIdx.x * 128;
  int arow = tid >> 1, ah = (tid & 1) * 64;
  int bk = tid >> 5,  bj = (tid & 31) * 4;
  float sc = scale ? scale[br + arow] : 1.0f;
  const float* Ap = A + (size_t)(br + arow)*HH + ah;
  #pragma unroll
  for (int c = 0; c < 64; c += 4){
    float4 av = *reinterpret_cast<const float4*>(Ap + c);
    As[ah+c+0][arow] = av.x * sc;
    As[ah+c+1][arow] = av.y * sc;
    As[ah+c+2][arow] = av.z * sc;
    As[ah+c+3][arow] = av.w * sc;
  }
  const float* Ws[3] = {W0, W1, W2};
  float*       Os[3] = {O0, O1, O2};
  for (int m3 = 0; m3 < 3; m3++){
    const float* W = Ws[m3];
    if (!W) break;
    u64 acc[8][4];
    #pragma unroll
    for (int i = 0; i < 8; i++)
      #pragma unroll
      for (int j = 0; j < 4; j++) acc[i][j] = 0ull;
    for (int kt = 0; kt < HH; kt += 8){
      __syncthreads();   // As ready (first iter) / Bs consumed (later iters)
      *reinterpret_cast<float4*>(&Bs[bk][bj]) =
          *reinterpret_cast<const float4*>(&W[(kt+bk)*HH + bj]);
      __syncthreads();
      #pragma unroll
      for (int k = 0; k < 8; k++){
        float4 a0 = *reinterpret_cast<const float4*>(&As[kt+k][ty*8]);
        float4 a1 = *reinterpret_cast<const float4*>(&As[kt+k][ty*8+4]);
        u64 ra2[8];
        ra2[0]=pkdup(a0.x); ra2[1]=pkdup(a0.y); ra2[2]=pkdup(a0.z); ra2[3]=pkdup(a0.w);
        ra2[4]=pkdup(a1.x); ra2[5]=pkdup(a1.y); ra2[6]=pkdup(a1.z); ra2[7]=pkdup(a1.w);
        ulonglong2 b0 = *reinterpret_cast<const ulonglong2*>(&Bs[k][tx*8]);
        ulonglong2 b1 = *reinterpret_cast<const ulonglong2*>(&Bs[k][tx*8+4]);
        u64 rb[4] = {b0.x, b0.y, b1.x, b1.y};
        #pragma unroll
        for (int i = 0; i < 8; i++)
          #pragma unroll
          for (int j = 0; j < 4; j++) fma2(acc[i][j], ra2[i], rb[j]);
      }
    }
    float* O = Os[m3];
    #pragma unroll
    for (int i = 0; i < 8; i++){
      int r = br + ty*8 + i;
      float2 v0 = up2(acc[i][0]), v1 = up2(acc[i][1]);
      float2 v2 = up2(acc[i][2]), v3 = up2(acc[i][3]);
      *reinterpret_cast<float4*>(&O[(size_t)r*HH + tx*8    ]) = make_float4(v0.x,v0.y,v1.x,v1.y);
      *reinterpret_cast<float4*>(&O[(size_t)r*HH + tx*8 + 4]) = make_float4(v2.x,v2.y,v3.x,v3.y);
    }
  }
}

// ---------------- SpMM aggregation + dnorm + bias + relu -> g_h, fused fp64 score proj ----
// warp per destination node, lane owns 4 contiguous features (float4)
__global__ void __launch_bounds__(256) k_spmm_relu(const float* __restrict__ t,
                                                   const float* __restrict__ bias,
                                                   const float* __restrict__ Wp){
  int gw = (blockIdx.x*blockDim.x + threadIdx.x) >> 5;
  int lane = threadIdx.x & 31;
  if (gw >= NN) return;
  int s0 = g_rowptr[gw], s1 = g_rowptr[gw+1];
  float4 a0 = make_float4(0,0,0,0), a1 = make_float4(0,0,0,0);
  int j = s0;
  for (; j + 1 < s1; j += 2){
    int c0 = g_col[j], c1 = g_col[j+1];
    float4 v0 = *reinterpret_cast<const float4*>(&t[(size_t)c0*HH + lane*4]);
    float4 v1 = *reinterpret_cast<const float4*>(&t[(size_t)c1*HH + lane*4]);
    a0.x += v0.x; a0.y += v0.y; a0.z += v0.z; a0.w += v0.w;
    a1.x += v1.x; a1.y += v1.y; a1.z += v1.z; a1.w += v1.w;
  }
  if (j < s1){
    int c0 = g_col[j];
    float4 v0 = *reinterpret_cast<const float4*>(&t[(size_t)c0*HH + lane*4]);
    a0.x += v0.x; a0.y += v0.y; a0.z += v0.z; a0.w += v0.w;
  }
  float dn = g_dnorm[gw];
  float4 b = *reinterpret_cast<const float4*>(&bias[lane*4]);
  float4 o;
  o.x = fmaxf((a0.x+a1.x)*dn + b.x, 0.f);
  o.y = fmaxf((a0.y+a1.y)*dn + b.y, 0.f);
  o.z = fmaxf((a0.z+a1.z)*dn + b.z, 0.f);
  o.w = fmaxf((a0.w+a1.w)*dn + b.w, 0.f);
  *reinterpret_cast<float4*>(&g_h[(size_t)gw*HH + lane*4]) = o;
  // fused SAGPool score projection in fp64: sv = dnorm * dot(h_row, Wp)
  // (top-k rank boundaries are the output's only discontinuity; minimize our score error)
  float4 w = *reinterpret_cast<const float4*>(&Wp[lane*4]);
  double p = (double)o.x*(double)w.x + (double)o.y*(double)w.y
           + (double)o.z*(double)w.z + (double)o.w*(double)w.w;
  #pragma unroll
  for (int off = 16; off > 0; off >>= 1) p += __shfl_xor_sync(0xffffffffu, p, off);
  if (lane == 0) g_sv[gw] = p * (double)dn;
}

// ---------------- per-graph: fp64 score agg + top-k (bitonic, stable desc) + tanh gate + gather
__global__ void __launch_bounds__(256) k_topk(const float* __restrict__ bp){
  __shared__ float sk[256];
  __shared__ int   si[256];
  __shared__ float stv[DIMS];
  int b = blockIdx.x, t = threadIdx.x;
  int n = b*NP + t;
  {
    int s0 = g_rowptr[n], s1 = g_rowptr[n+1];
    double s = 0.0;
    for (int j = s0; j < s1; j++) s += g_sv[g_col[j]];
    sk[t] = (float)(s * (double)g_dnorm[n] + (double)bp[0]);
    si[t] = t;
  }
  __syncthreads();
  for (int k = 2; k <= 256; k <<= 1){
    for (int j = k >> 1; j > 0; j >>= 1){
      int ixj = t ^ j;
      if (ixj > t){
        bool dir = ((t & k) == 0);
        float ka = sk[t], kb = sk[ixj];
        int   ia = si[t], ib = si[ixj];
        bool before = (ka > kb) || (ka == kb && ia < ib);  // stable: tie -> lower idx
        bool doswap = dir ? (!before) : before;
        if (doswap){ sk[t] = kb; sk[ixj] = ka; si[t] = ib; si[ixj] = ia; }
      }
      __syncthreads();
    }
  }
  if (t < DIMS) stv[t] = tanhf(sk[t]);
  __syncthreads();
  // gather + gate: xp[b, rr, :] = h[b*NP + si[rr], :] * tanh(val[rr])
  for (int i = t; i < DIMS*HH/4; i += 256){
    int rr = i >> 5;
    int c  = (i & 31) * 4;
    float tv = stv[rr];
    float4 v = *reinterpret_cast<const float4*>(&g_h[(size_t)(b*NP + si[rr])*HH + c]);
    float4 o = make_float4(v.x*tv, v.y*tv, v.z*tv, v.w*tv);
    *reinterpret_cast<float4*>(&g_xp[(size_t)(b*DIMS + rr)*HH + c]) = o;
  }
}

// ---------------- MHSA per (head, graph): lazy-rescale online softmax, packed f32x2 ----------------
__global__ void __launch_bounds__(128) k_attn(int L){
  int hd = blockIdx.x, b = blockIdx.y;
  __shared__ __align__(16) float Ks[DIMS][DKK];
  __shared__ __align__(16) float Vs[DIMS][DKK];
  int t = threadIdx.x;  // query row
  size_t rowbase = (size_t)(b*DIMS + t)*HH + hd*DKK;
  #pragma unroll
  for (int d = 0; d < DKK; d += 4){
    *reinterpret_cast<float4*>(&Ks[t][d]) = *reinterpret_cast<const float4*>(&g_k[rowbase + d]);
    *reinterpret_cast<float4*>(&Vs[t][d]) = *reinterpret_cast<const float4*>(&g_v[rowbase + d]);
  }
  u64 q2[8];
  {
    const u64* qp = reinterpret_cast<const u64*>(&g_q[rowbase]);
    #pragma unroll
    for (int i = 0; i < 8; i++) q2[i] = qp[i];
  }
  __syncthreads();
  float m = -1e30f, l = 0.f;
  u64 o2[8];
  #pragma unroll
  for (int i = 0; i < 8; i++) o2[i] = 0ull;
  for (int j = 0; j < DIMS; j++){
    u64 s2 = 0ull;
    const u64* kp = reinterpret_cast<const u64*>(&Ks[j][0]);
    #pragma unroll
    for (int i = 0; i < 8; i++) fma2(s2, q2[i], kp[i]);
    float2 sv = up2(s2);
    float s = (sv.x + sv.y) * 0.25f;   // 1/sqrt(16)
    if (s > m){
      float corr = __expf(m - s);      // first iter: exp(-inf) = 0
      u64 c2 = pkdup(corr);
      l *= corr;
      #pragma unroll
      for (int i = 0; i < 8; i++) o2[i] = mul2(o2[i], c2);
      m = s;
    }
    float p = __expf(s - m);
    l += p;
    u64 p2 = pkdup(p);
    const u64* vp = reinterpret_cast<const u64*>(&Vs[j][0]);
    #pragma unroll
    for (int i = 0; i < 8; i++) fma2(o2[i], p2, vp[i]);
  }
  float inv = 1.f / l;
  float* op = &g_xs[((size_t)(b*3 + L)*DIMS + t)*HH + hd*DKK];
  #pragma unroll
  for (int i = 0; i < 8; i += 2){
    float2 v0 = up2(o2[i]), v1 = up2(o2[i+1]);
    *reinterpret_cast<float4*>(&op[2*i]) = make_float4(v0.x*inv, v0.y*inv, v1.x*inv, v1.y*inv);
  }
}

// ---------------- head: conv1 -> relu -> maxpool -> conv2 -> relu -> fc -> relu -> fc -> log_softmax
// one block per graph, 128 threads (thread = feature index w for conv1)
__global__ void __launch_bounds__(128) k_head(const float* __restrict__ Wc1, const float* __restrict__ bc1,
                                              const float* __restrict__ Wc2, const float* __restrict__ bc2,
                                              const float* __restrict__ Wl1, const float* __restrict__ bl1,
                                              const float* __restrict__ Wl2, const float* __restrict__ bl2,
                                              float* __restrict__ out){
  extern __shared__ __align__(16) float sm[];
  float* Wc1T = sm;             // [384][32] transposed
  float* sy   = sm + 12288;     // [32][128]
  float* sy2  = sy + 4096;      // [32][64]
  float* sz   = sy2 + 2048;     // [64]
  float* sz2  = sz + 64;        // [64]
  float* spar = sz2 + 64;       // [2][64] conv2 partials
  int b = blockIdx.x, t = threadIdx.x;
  for (int i = t; i < 12288; i += 128){
    int o = i / 384, cd = i % 384;
    Wc1T[cd*32 + o] = Wc1[i];
  }
  __syncthreads();
  // conv1: acc over (c,d) flattened = 384, packed pairs over output channel o
  u64 acc[16];
  #pragma unroll
  for (int o = 0; o < 16; o++) acc[o] = 0ull;
  const float* xb = &g_xs[(size_t)b*3*DIMS*HH];
  for (int cd = 0; cd < 384; cd++){
    u64 vd = pkdup(xb[(size_t)cd*HH + t]);
    const u64* wr = reinterpret_cast<const u64*>(&Wc1T[cd*32]);
    #pragma unroll
    for (int o = 0; o < 16; o++) fma2(acc[o], vd, wr[o]);
  }
  #pragma unroll
  for (int o = 0; o < 16; o++){
    float2 v = up2(acc[o]);
    sy[(2*o  )*128 + t] = fmaxf(v.x + bc1[2*o  ], 0.f);
    sy[(2*o+1)*128 + t] = fmaxf(v.y + bc1[2*o+1], 0.f);
  }
  __syncthreads();
  // maxpool (1,2)
  for (int i = t; i < C1N*64; i += 128){
    int o = i / 64, w = i % 64;
    sy2[i] = fmaxf(sy[o*128 + 2*w], sy[o*128 + 2*w + 1]);
  }
  __syncthreads();
  // conv2: 2048-long dot per output, split across 2 threads, packed pairs
  {
    int o = t & 63, half = t >> 6;
    const u64* w2 = reinterpret_cast<const u64*>(&Wc2[(size_t)o*2048 + half*1024]);
    const u64* y2 = reinterpret_cast<const u64*>(&sy2[half*1024]);
    u64 s2a = 0ull, s2b = 0ull;
    #pragma unroll 4
    for (int i = 0; i < 512; i += 2){
      fma2(s2a, y2[i],   w2[i]);
      fma2(s2b, y2[i+1], w2[i+1]);
    }
    float2 va = up2(s2a), vb = up2(s2b);
    spar[half*64 + o] = (va.x + va.y) + (vb.x + vb.y);
  }
  __syncthreads();
  if (t < C2N) sz[t] = fmaxf(spar[t] + spar[64 + t] + bc2[t], 0.f);
  __syncthreads();
  if (t < C2N){
    float s = bl1[t];
    for (int i = 0; i < 64; i++) s += sz[i] * Wl1[i*64 + t];
    sz2[t] = fmaxf(s, 0.f);
  }
  __syncthreads();
  if (t < NCN){
    float s = bl2[t];
    for (int i = 0; i < 64; i++) s += sz2[i] * Wl2[i*NCN + t];
    sz[t] = s;  // logits
  }
  __syncthreads();
  if (t == 0){
    float mx = -1e30f;
    for (int i = 0; i < NCN; i++) mx = fmaxf(mx, sz[i]);
    float se = 0.f;
    for (int i = 0; i < NCN; i++) se += expf(sz[i] - mx);
    float lse = mx + logf(se);
    for (int i = 0; i < NCN; i++) out[b*NCN + i] = sz[i] - lse;
  }
}

// ---------------- host ----------------
extern "C" void kernel_launch(void* const* d_in, const int* in_sizes, int n_in,
                              void* d_out, int out_size){
  (void)in_sizes; (void)n_in; (void)out_size;
  const float* x   = (const float*)d_in[0];
  const int*   src = (const int*)  d_in[1];
  const int*   dst = (const int*)  d_in[2];
  const float* Wg[3] = {(const float*)d_in[3], (const float*)d_in[5], (const float*)d_in[7]};
  const float* bg[3] = {(const float*)d_in[4], (const float*)d_in[6], (const float*)d_in[8]};
  const float* Wp  = (const float*)d_in[9];
  const float* bp  = (const float*)d_in[10];
  const float* Wq  = (const float*)d_in[11];
  const float* Wk  = (const float*)d_in[12];
  const float* Wv  = (const float*)d_in[13];
  const float* Wc1 = (const float*)d_in[14];
  const float* bc1 = (const float*)d_in[15];
  const float* Wc2 = (const float*)d_in[16];
  const float* bc2 = (const float*)d_in[17];
  const float* Wl1 = (const float*)d_in[18];
  const float* bl1 = (const float*)d_in[19];
  const float* Wl2 = (const float*)d_in[20];
  const float* bl2 = (const float*)d_in[21];
  float* out = (float*)d_out;

  void *p_t, *p_h, *p_xp, *p_q, *p_k, *p_v, *p_dnorm;
  cudaGetSymbolAddress(&p_t, g_t);
  cudaGetSymbolAddress(&p_h, g_h);
  cudaGetSymbolAddress(&p_xp, g_xp);
  cudaGetSymbolAddress(&p_q, g_q);
  cudaGetSymbolAddress(&p_k, g_k);
  cudaGetSymbolAddress(&p_v, g_v);
  cudaGetSymbolAddress(&p_dnorm, g_dnorm);

  // CSR build (deterministic: counts exact, rows canonically sorted)
  k_zero_cnt<<<(NN+255)/256, 256>>>();
  k_count<<<(EE+255)/256, 256>>>(dst);
  k_scan<<<1, 1024>>>();
  k_fill<<<(EE+255)/256, 256>>>(src, dst);
  k_sort_dnorm<<<(NN+127)/128, 128>>>();

  const float* hin = x;
  for (int L = 0; L < 3; L++){
    k_gemm3<<<NN/128, 256>>>(hin, (const float*)p_dnorm, Wg[L], (float*)p_t,
                             nullptr, nullptr, nullptr, nullptr);
    k_spmm_relu<<<NN/8, 256>>>((const float*)p_t, bg[L], Wp);
    k_topk<<<BB, 256>>>(bp);
    k_gemm3<<<(BB*DIMS)/128, 256>>>((const float*)p_xp, nullptr,
                                    Wq, (float*)p_q, Wk, (float*)p_k, Wv, (float*)p_v);
    k_attn<<<dim3(NHEADS, BB), 128>>>(L);
    hin = (const float*)p_h;
  }

  cudaFuncSetAttribute(k_head, cudaFuncAttributeMaxDynamicSharedMemorySize, 76*1024);
  k_head<<<BB, 128, 75264>>>(Wc1, bc1, Wc2, bc2, Wl1, bl1, Wl2, bl2, out);
}

// round 7
// speedup vs baseline: 1.1532x; 1.1532x over previous
#include <cuda_runtime.h>
#include <math.h>

#define BB 128
#define NP 256
#define NN (BB*NP)        // 32768 nodes
#define EP 2048
#define EPG (2*EP)        // 4096 edges per graph (symmetrized)
#define EE (BB*EPG)       // 524288 edges total
#define HH 128
#define DIMS 128
#define NHEADS 8
#define DKK 16
#define C1N 32
#define C2N 64
#define NCN 10

typedef unsigned long long u64;

// ---------------- packed f32x2 helpers (FFMA2 path; ptxas never emits these from C++) ----
__device__ __forceinline__ u64 pk2(float lo, float hi){
  u64 r; asm("mov.b64 %0,{%1,%2};":"=l"(r):"f"(lo),"f"(hi)); return r;
}
__device__ __forceinline__ u64 pkdup(float v){ return pk2(v, v); }
__device__ __forceinline__ float2 up2(u64 v){
  float2 r; asm("mov.b64 {%0,%1},%2;":"=f"(r.x),"=f"(r.y):"l"(v)); return r;
}
__device__ __forceinline__ void fma2(u64 &d, u64 a, u64 b){
  asm("fma.rn.f32x2 %0,%1,%2,%0;":"+l"(d):"l"(a),"l"(b));
}
__device__ __forceinline__ u64 mul2(u64 a, u64 b){
  u64 d; asm("mul.rn.f32x2 %0,%1,%2;":"=l"(d):"l"(a),"l"(b)); return d;
}
__device__ __forceinline__ float ex2(float x){
  float r; asm("ex2.approx.ftz.f32 %0,%1;":"=f"(r):"f"(x)); return r;
}

// ---------------- scratch (device globals; no allocations allowed) ----------------
__device__ float  g_dnorm[NN];
__device__ int    g_rowptr[NN+1];
__device__ int    g_col[EE];
__device__ float  g_h[NN*HH];          // current node features
__device__ float  g_t[NN*HH];          // (dnorm*h)@W before aggregation
__device__ double g_sv[NN];            // score pre-aggregation (dnorm*h@Wp), fp64
__device__ int    g_idx[BB*DIMS];      // global node ids of top-k (ordered)
__device__ float  g_tanhv[BB*DIMS];    // tanh(topk values)
__device__ float  g_q[BB*DIMS*HH];
__device__ float  g_k[BB*DIMS*HH];
__device__ float  g_v[BB*DIMS*HH];
__device__ float  g_xs[BB*3*DIMS*HH];  // stacked MHSA outputs [B][3][DIMS][H]

// ---------------- fused CSR build: one block per graph, all in shared ----------------
// Each graph owns exactly EPG=4096 edges, endpoints confined to its 256-node range,
// so rowptr base is b*EPG with a purely local scan. No global atomics anywhere.
// Rows are canonically sorted ascending -> deterministic float summation downstream.
__global__ void __launch_bounds__(256) k_build_csr(const int* __restrict__ src,
                                                   const int* __restrict__ dst){
  __shared__ int scnt[256];   // histogram -> inclusive scan
  __shared__ int spre[256];   // exclusive prefix
  __shared__ int ssz[256];    // row length
  __shared__ int sofs[256];   // fill cursors
  __shared__ int scol[EPG];   // staged column indices (16KB)
  int b = blockIdx.x, t = threadIdx.x;
  int nbase = b*NP;
  scnt[t] = 0; sofs[t] = 0;
  __syncthreads();
  // histogram dst (two 2048-edge halves: forward and reversed copies)
  const int e0b = b*EP, e1b = BB*EP + b*EP;
  for (int i = t; i < EP; i += 256){
    atomicAdd(&scnt[dst[e0b + i] - nbase], 1);
    atomicAdd(&scnt[dst[e1b + i] - nbase], 1);
  }
  __syncthreads();
  int cnt = scnt[t];
  ssz[t] = cnt;
  // Hillis-Steele inclusive scan over 256 bins
  for (int off = 1; off < 256; off <<= 1){
    int u = 0;
    if (t >= off) u = scnt[t - off];
    __syncthreads();
    scnt[t] += u;
    __syncthreads();
  }
  spre[t] = scnt[t] - cnt;   // exclusive prefix
  __syncthreads();
  // scatter src values into shared via per-node cursors (order fixed by sort below)
  for (int i = t; i < EP; i += 256){
    int ld0 = dst[e0b + i] - nbase;
    scol[spre[ld0] + atomicAdd(&sofs[ld0], 1)] = src[e0b + i];
    int ld1 = dst[e1b + i] - nbase;
    scol[spre[ld1] + atomicAdd(&sofs[ld1], 1)] = src[e1b + i];
  }
  __syncthreads();
  // per-thread insertion sort of its row (avg len 16) in shared
  {
    int s0 = spre[t], s1 = s0 + ssz[t];
    for (int i = s0 + 1; i < s1; i++){
      int key = scol[i]; int j = i - 1;
      while (j >= s0 && scol[j] > key){ scol[j+1] = scol[j]; j--; }
      scol[j+1] = key;
    }
  }
  g_rowptr[nbase + t] = b*EPG + spre[t];
  g_dnorm[nbase + t] = rsqrtf(fmaxf((float)ssz[t], 1.0f));
  if (b == 0 && t == 0) g_rowptr[NN] = EE;
  __syncthreads();
  // coalesced write-out
  for (int i = t; i < EPG; i += 256) g_col[b*EPG + i] = scol[i];
}

// ---------------- GEMM core: O[128 rows, 128] = As @ W[128,128], fp32, FFMA2 ----------------
// As is [k][m] resident; 256 threads, each computes 8x8 (as 8x4 packed pairs).
__device__ __forceinline__ void gemm_main(float (*As)[128], float (*Bs)[128],
                                          const float* __restrict__ W,
                                          float* __restrict__ O, int br, int tid){
  int tx = tid & 15, ty = tid >> 4;
  int bk = tid >> 5, bj = (tid & 31) * 4;
  u64 acc[8][4];
  #pragma unroll
  for (int i = 0; i < 8; i++)
    #pragma unroll
    for (int j = 0; j < 4; j++) acc[i][j] = 0ull;
  for (int kt = 0; kt < HH; kt += 8){
    __syncthreads();   // As ready (first iter) / Bs consumed (later iters)
    *reinterpret_cast<float4*>(&Bs[bk][bj]) =
        *reinterpret_cast<const float4*>(&W[(kt+bk)*HH + bj]);
    __syncthreads();
    #pragma unroll
    for (int k = 0; k < 8; k++){
      float4 a0 = *reinterpret_cast<const float4*>(&As[kt+k][ty*8]);
      float4 a1 = *reinterpret_cast<const float4*>(&As[kt+k][ty*8+4]);
      u64 ra2[8];
      ra2[0]=pkdup(a0.x); ra2[1]=pkdup(a0.y); ra2[2]=pkdup(a0.z); ra2[3]=pkdup(a0.w);
      ra2[4]=pkdup(a1.x); ra2[5]=pkdup(a1.y); ra2[6]=pkdup(a1.z); ra2[7]=pkdup(a1.w);
      ulonglong2 b0 = *reinterpret_cast<const ulonglong2*>(&Bs[k][tx*8]);
      ulonglong2 b1 = *reinterpret_cast<const ulonglong2*>(&Bs[k][tx*8+4]);
      u64 rb[4] = {b0.x, b0.y, b1.x, b1.y};
      #pragma unroll
      for (int i = 0; i < 8; i++)
        #pragma unroll
        for (int j = 0; j < 4; j++) fma2(acc[i][j], ra2[i], rb[j]);
    }
  }
  #pragma unroll
  for (int i = 0; i < 8; i++){
    int r = br + ty*8 + i;
    float2 v0 = up2(acc[i][0]), v1 = up2(acc[i][1]);
    float2 v2 = up2(acc[i][2]), v3 = up2(acc[i][3]);
    *reinterpret_cast<float4*>(&O[(size_t)r*HH + tx*8    ]) = make_float4(v0.x,v0.y,v1.x,v1.y);
    *reinterpret_cast<float4*>(&O[(size_t)r*HH + tx*8 + 4]) = make_float4(v2.x,v2.y,v3.x,v3.y);
  }
}

// node path: O = (A .* dnorm) @ W,  grid.x = NN/128
__global__ void __launch_bounds__(256) k_gemm_node(const float* __restrict__ A,
                                                   const float* __restrict__ W,
                                                   float* __restrict__ O){
  __shared__ float As[128][128];
  __shared__ float Bs[8][128];
  int tid = threadIdx.x;
  int br = blockIdx.x * 128;
  int arow = tid >> 1, ah = (tid & 1) * 64;
  float sc = g_dnorm[br + arow];
  const float* Ap = A + (size_t)(br + arow)*HH + ah;
  #pragma unroll
  for (int c = 0; c < 64; c += 4){
    float4 av = *reinterpret_cast<const float4*>(Ap + c);
    As[ah+c+0][arow] = av.x * sc;
    As[ah+c+1][arow] = av.y * sc;
    As[ah+c+2][arow] = av.z * sc;
    As[ah+c+3][arow] = av.w * sc;
  }
  gemm_main(As, Bs, W, O, br, tid);
}

// QKV path: rows gathered via g_idx, gated by tanh; grid = (BB*DIMS/128, 3)
__global__ void __launch_bounds__(256) k_gemm_qkv(const float* __restrict__ W0,
                                                  const float* __restrict__ W1,
                                                  const float* __restrict__ W2){
  __shared__ float As[128][128];
  __shared__ float Bs[8][128];
  int tid = threadIdx.x;
  int br = blockIdx.x * 128;
  int arow = tid >> 1, ah = (tid & 1) * 64;
  int srcrow = g_idx[br + arow];       // fused gather
  float sc = g_tanhv[br + arow];       // fused tanh gate
  const float* Ap = g_h + (size_t)srcrow*HH + ah;
  #pragma unroll
  for (int c = 0; c < 64; c += 4){
    float4 av = *reinterpret_cast<const float4*>(Ap + c);
    As[ah+c+0][arow] = av.x * sc;
    As[ah+c+1][arow] = av.y * sc;
    As[ah+c+2][arow] = av.z * sc;
    As[ah+c+3][arow] = av.w * sc;
  }
  const float* W = (blockIdx.y == 0) ? W0 : (blockIdx.y == 1) ? W1 : W2;
  float*       O = (blockIdx.y == 0) ? g_q : (blockIdx.y == 1) ? g_k : g_v;
  gemm_main(As, Bs, W, O, br, tid);
}

// ---------------- SpMM aggregation + dnorm + bias + relu -> g_h, fused fp64 score proj ----
// warp per destination node, lane owns 4 contiguous features (float4)
__global__ void __launch_bounds__(256) k_spmm_relu(const float* __restrict__ bias,
                                                   const float* __restrict__ Wp){
  int gw = (blockIdx.x*blockDim.x + threadIdx.x) >> 5;
  int lane = threadIdx.x & 31;
  if (gw >= NN) return;
  const float* t = g_t;
  int s0 = g_rowptr[gw], s1 = g_rowptr[gw+1];
  float4 a0 = make_float4(0,0,0,0), a1 = make_float4(0,0,0,0);
  float4 a2 = make_float4(0,0,0,0), a3 = make_float4(0,0,0,0);
  int j = s0;
  for (; j + 3 < s1; j += 4){
    int c0 = g_col[j], c1 = g_col[j+1], c2 = g_col[j+2], c3 = g_col[j+3];
    float4 v0 = *reinterpret_cast<const float4*>(&t[(size_t)c0*HH + lane*4]);
    float4 v1 = *reinterpret_cast<const float4*>(&t[(size_t)c1*HH + lane*4]);
    float4 v2 = *reinterpret_cast<const float4*>(&t[(size_t)c2*HH + lane*4]);
    float4 v3 = *reinterpret_cast<const float4*>(&t[(size_t)c3*HH + lane*4]);
    a0.x += v0.x; a0.y += v0.y; a0.z += v0.z; a0.w += v0.w;
    a1.x += v1.x; a1.y += v1.y; a1.z += v1.z; a1.w += v1.w;
    a2.x += v2.x; a2.y += v2.y; a2.z += v2.z; a2.w += v2.w;
    a3.x += v3.x; a3.y += v3.y; a3.z += v3.z; a3.w += v3.w;
  }
  for (; j < s1; j++){
    int c0 = g_col[j];
    float4 v0 = *reinterpret_cast<const float4*>(&t[(size_t)c0*HH + lane*4]);
    a0.x += v0.x; a0.y += v0.y; a0.z += v0.z; a0.w += v0.w;
  }
  float dn = g_dnorm[gw];
  float4 b = *reinterpret_cast<const float4*>(&bias[lane*4]);
  float4 o;
  o.x = fmaxf(((a0.x+a1.x)+(a2.x+a3.x))*dn + b.x, 0.f);
  o.y = fmaxf(((a0.y+a1.y)+(a2.y+a3.y))*dn + b.y, 0.f);
  o.z = fmaxf(((a0.z+a1.z)+(a2.z+a3.z))*dn + b.z, 0.f);
  o.w = fmaxf(((a0.w+a1.w)+(a2.w+a3.w))*dn + b.w, 0.f);
  *reinterpret_cast<float4*>(&g_h[(size_t)gw*HH + lane*4]) = o;
  // fused SAGPool score projection in fp64: sv = dnorm * dot(h_row, Wp)
  // (top-k rank boundaries are the output's only discontinuity; minimize our score error)
  float4 w = *reinterpret_cast<const float4*>(&Wp[lane*4]);
  double p = (double)o.x*(double)w.x + (double)o.y*(double)w.y
           + (double)o.z*(double)w.z + (double)o.w*(double)w.w;
  #pragma unroll
  for (int off = 16; off > 0; off >>= 1) p += __shfl_xor_sync(0xffffffffu, p, off);
  if (lane == 0) g_sv[gw] = p * (double)dn;
}

// ---------------- per-graph: fp64 score agg + top-k (bitonic, stable desc) -> idx + tanh ----
__global__ void __launch_bounds__(256) k_topk(const float* __restrict__ bp){
  __shared__ float sk[256];
  __shared__ int   si[256];
  int b = blockIdx.x, t = threadIdx.x;
  int n = b*NP + t;
  {
    int s0 = g_rowptr[n], s1 = g_rowptr[n+1];
    double s = 0.0;
    for (int j = s0; j < s1; j++) s += g_sv[g_col[j]];
    sk[t] = (float)(s * (double)g_dnorm[n] + (double)bp[0]);
    si[t] = t;
  }
  __syncthreads();
  for (int k = 2; k <= 256; k <<= 1){
    for (int j = k >> 1; j > 0; j >>= 1){
      int ixj = t ^ j;
      if (ixj > t){
        bool dir = ((t & k) == 0);
        float ka = sk[t], kb = sk[ixj];
        int   ia = si[t], ib = si[ixj];
        bool before = (ka > kb) || (ka == kb && ia < ib);  // stable: tie -> lower idx
        bool doswap = dir ? (!before) : before;
        if (doswap){ sk[t] = kb; sk[ixj] = ka; si[t] = ib; si[ixj] = ia; }
      }
      __syncthreads();
    }
  }
  if (t < DIMS){
    g_idx[b*DIMS + t]   = b*NP + si[t];
    g_tanhv[b*DIMS + t] = tanhf(sk[t]);
  }
}

// ---------------- MHSA per (head, graph): lazy-rescale online softmax in log2 domain ----------
__global__ void __launch_bounds__(128) k_attn(int L){
  int hd = blockIdx.x, b = blockIdx.y;
  __shared__ __align__(16) float Ks[DIMS][DKK];
  __shared__ __align__(16) float Vs[DIMS][DKK];
  int t = threadIdx.x;  // query row
  size_t rowbase = (size_t)(b*DIMS + t)*HH + hd*DKK;
  #pragma unroll
  for (int d = 0; d < DKK; d += 4){
    *reinterpret_cast<float4*>(&Ks[t][d]) = *reinterpret_cast<const float4*>(&g_k[rowbase + d]);
    *reinterpret_cast<float4*>(&Vs[t][d]) = *reinterpret_cast<const float4*>(&g_v[rowbase + d]);
  }
  // pre-scale q by (1/sqrt(dk)) * log2(e): softmax computed with ex2 (exact same weights)
  const float QS = 0.25f * 1.4426950408889634f;
  u64 q2[8];
  #pragma unroll
  for (int d = 0; d < DKK; d += 4){
    float4 qv = *reinterpret_cast<const float4*>(&g_q[rowbase + d]);
    q2[d/2  ] = pk2(qv.x*QS, qv.y*QS);
    q2[d/2+1] = pk2(qv.z*QS, qv.w*QS);
  }
  __syncthreads();
  float m = -1e30f, l = 0.f;
  u64 o2[8];
  #pragma unroll
  for (int i = 0; i < 8; i++) o2[i] = 0ull;
  #pragma unroll 2
  for (int j = 0; j < DIMS; j++){
    const ulonglong2* kp = reinterpret_cast<const ulonglong2*>(&Ks[j][0]);
    u64 sa = 0ull, sb = 0ull;
    #pragma unroll
    for (int i = 0; i < 4; i++){
      ulonglong2 kk = kp[i];
      fma2(sa, q2[2*i],   kk.x);
      fma2(sb, q2[2*i+1], kk.y);
    }
    float2 sva = up2(sa), svb = up2(sb);
    float s = (sva.x + svb.x) + (sva.y + svb.y);   // log2-domain score
    if (s > m){
      float corr = ex2(m - s);                     // first iter: ex2(-huge) = 0
      u64 c2 = pkdup(corr);
      l *= corr;
      #pragma unroll
      for (int i = 0; i < 8; i++) o2[i] = mul2(o2[i], c2);
      m = s;
    }
    float p = ex2(s - m);
    l += p;
    u64 p2 = pkdup(p);
    const ulonglong2* vp = reinterpret_cast<const ulonglong2*>(&Vs[j][0]);
    #pragma unroll
    for (int i = 0; i < 4; i++){
      ulonglong2 vv = vp[i];
      fma2(o2[2*i],   p2, vv.x);
      fma2(o2[2*i+1], p2, vv.y);
    }
  }
  float inv = 1.f / l;
  float* op = &g_xs[((size_t)(b*3 + L)*DIMS + t)*HH + hd*DKK];
  #pragma unroll
  for (int i = 0; i < 8; i += 2){
    float2 v0 = up2(o2[i]), v1 = up2(o2[i+1]);
    *reinterpret_cast<float4*>(&op[2*i]) = make_float4(v0.x*inv, v0.y*inv, v1.x*inv, v1.y*inv);
  }
}

// ---------------- head: conv1 -> relu -> maxpool -> conv2 -> relu -> fc -> relu -> fc -> log_softmax
// one block per graph, 128 threads (thread = feature index w for conv1)
__global__ void __launch_bounds__(128) k_head(const float* __restrict__ Wc1, const float* __restrict__ bc1,
                                              const float* __restrict__ Wc2, const float* __restrict__ bc2,
                                              const float* __restrict__ Wl1, const float* __restrict__ bl1,
                                              const float* __restrict__ Wl2, const float* __restrict__ bl2,
                                              float* __restrict__ out){
  extern __shared__ __align__(16) float sm[];
  float* Wc1T = sm;             // [384][32] transposed
  float* sy   = sm + 12288;     // [32][128]
  float* sy2  = sy + 4096;      // [32][64]
  float* sz   = sy2 + 2048;     // [64]
  float* sz2  = sz + 64;        // [64]
  float* spar = sz2 + 64;       // [2][64] conv2 partials
  int b = blockIdx.x, t = threadIdx.x;
  for (int i = t; i < 12288; i += 128){
    int o = i / 384, cd = i % 384;
    Wc1T[cd*32 + o] = Wc1[i];
  }
  __syncthreads();
  // conv1: acc over (c,d) flattened = 384, packed pairs over output channel o
  u64 acc[16];
  #pragma unroll
  for (int o = 0; o < 16; o++) acc[o] = 0ull;
  const float* xb = &g_xs[(size_t)b*3*DIMS*HH];
  for (int cd = 0; cd < 384; cd++){
    u64 vd = pkdup(xb[(size_t)cd*HH + t]);
    const u64* wr = reinterpret_cast<const u64*>(&Wc1T[cd*32]);
    #pragma unroll
    for (int o = 0; o < 16; o++) fma2(acc[o], vd, wr[o]);
  }
  #pragma unroll
  for (int o = 0; o < 16; o++){
    float2 v = up2(acc[o]);
    sy[(2*o  )*128 + t] = fmaxf(v.x + bc1[2*o  ], 0.f);
    sy[(2*o+1)*128 + t] = fmaxf(v.y + bc1[2*o+1], 0.f);
  }
  __syncthreads();
  // maxpool (1,2)
  for (int i = t; i < C1N*64; i += 128){
    int o = i / 64, w = i % 64;
    sy2[i] = fmaxf(sy[o*128 + 2*w], sy[o*128 + 2*w + 1]);
  }
  __syncthreads();
  // conv2: 2048-long dot per output, split across 2 threads, packed pairs
  {
    int o = t & 63, half = t >> 6;
    const u64* w2 = reinterpret_cast<const u64*>(&Wc2[(size_t)o*2048 + half*1024]);
    const u64* y2 = reinterpret_cast<const u64*>(&sy2[half*1024]);
    u64 s2a = 0ull, s2b = 0ull;
    #pragma unroll 4
    for (int i = 0; i < 512; i += 2){
      fma2(s2a, y2[i],   w2[i]);
      fma2(s2b, y2[i+1], w2[i+1]);
    }
    float2 va = up2(s2a), vb = up2(s2b);
    spar[half*64 + o] = (va.x + va.y) + (vb.x + vb.y);
  }
  __syncthreads();
  if (t < C2N) sz[t] = fmaxf(spar[t] + spar[64 + t] + bc2[t], 0.f);
  __syncthreads();
  if (t < C2N){
    float s = bl1[t];
    for (int i = 0; i < 64; i++) s += sz[i] * Wl1[i*64 + t];
    sz2[t] = fmaxf(s, 0.f);
  }
  __syncthreads();
  if (t < NCN){
    float s = bl2[t];
    for (int i = 0; i < 64; i++) s += sz2[i] * Wl2[i*NCN + t];
    sz[t] = s;  // logits
  }
  __syncthreads();
  if (t == 0){
    float mx = -1e30f;
    for (int i = 0; i < NCN; i++) mx = fmaxf(mx, sz[i]);
    float se = 0.f;
    for (int i = 0; i < NCN; i++) se += expf(sz[i] - mx);
    float lse = mx + logf(se);
    for (int i = 0; i < NCN; i++) out[b*NCN + i] = sz[i] - lse;
  }
}

// ---------------- host ----------------
extern "C" void kernel_launch(void* const* d_in, const int* in_sizes, int n_in,
                              void* d_out, int out_size){
  (void)in_sizes; (void)n_in; (void)out_size;
  const float* x   = (const float*)d_in[0];
  const int*   src = (const int*)  d_in[1];
  const int*   dst = (const int*)  d_in[2];
  const float* Wg[3] = {(const float*)d_in[3], (const float*)d_in[5], (const float*)d_in[7]};
  const float* bg[3] = {(const float*)d_in[4], (const float*)d_in[6], (const float*)d_in[8]};
  const float* Wp  = (const float*)d_in[9];
  const float* bp  = (const float*)d_in[10];
  const float* Wq  = (const float*)d_in[11];
  const float* Wk  = (const float*)d_in[12];
  const float* Wv  = (const float*)d_in[13];
  const float* Wc1 = (const float*)d_in[14];
  const float* bc1 = (const float*)d_in[15];
  const float* Wc2 = (const float*)d_in[16];
  const float* bc2 = (const float*)d_in[17];
  const float* Wl1 = (const float*)d_in[18];
  const float* bl1 = (const float*)d_in[19];
  const float* Wl2 = (const float*)d_in[20];
  const float* bl2 = (const float*)d_in[21];
  float* out = (float*)d_out;

  void *p_t, *p_h;
  cudaGetSymbolAddress(&p_t, g_t);
  cudaGetSymbolAddress(&p_h, g_h);

  // CSR build: single fused kernel (per-graph shared-memory histogram/scan/fill/sort)
  k_build_csr<<<BB, 256>>>(src, dst);

  const float* hin = x;
  for (int L = 0; L < 3; L++){
    k_gemm_node<<<NN/128, 256>>>(hin, Wg[L], (float*)p_t);
    k_spmm_relu<<<NN/8, 256>>>(bg[L], Wp);
    k_topk<<<BB, 256>>>(bp);
    k_gemm_qkv<<<dim3((BB*DIMS)/128, 3), 256>>>(Wq, Wk, Wv);
    k_attn<<<dim3(NHEADS, BB), 128>>>(L);
    hin = (const float*)p_h;
  }

  cudaFuncSetAttribute(k_head, cudaFuncAttributeMaxDynamicSharedMemorySize, 76*1024);
  k_head<<<BB, 128, 75264>>>(Wc1, bc1, Wc2, bc2, Wl1, bl1, Wl2, bl2, out);
}